// round 13
// baseline (speedup 1.0000x reference)
#include <cuda_runtime.h>

#define NQ 12
#define BT 32    // one warp per CTA, 1 batch element per thread -> 256 CTAs

__device__ __forceinline__ float2 cmulc(float2 a, float2 b) {
    return make_float2(a.x * b.x - a.y * b.y, a.x * b.y + a.y * b.x);
}
__device__ __forceinline__ float2 caddc(float2 a, float2 b) {
    return make_float2(a.x + b.x, a.y + b.y);
}

// Single kernel: bond-dimension-4 transfer-matrix (MPS) contraction.
//
// amp_j(b) = sum_{a,b,n} G2[g(j),a] G1[g(a),b] G0[g(b),n] psi0[n],
// g(n) = n ^ (n>>1) is bit-local, psi0 is a product state, so the amplitude
// is a chain of twelve 4x4 complex transfer matrices over bond (a_p, b_p).
// Batch-independent K tensors (368 complex entries) built per CTA in shared.
__global__ __launch_bounds__(BT)
void qnn_mps_kernel(const float* __restrict__ x,
                    const float* __restrict__ params,
                    float* __restrict__ out, int B)
{
    __shared__ float2 sU[3][12][4];        // fused gates  [layer][wire][r*2+s]
    __shared__ float2 sK[11][2][4][4];     // [p-1][n-bit s][sigma][sigma']
    __shared__ float2 sKap[2][2][4];       // p=0 row-summed: [j][s][sigma']
    __shared__ float  sX[BT * NQ];         // staged x rows for this block

    const int tid = threadIdx.x;

    // ---- coalesced x staging: BT*12 floats = BT*3 float4 loads ------------
    {
        const float4* x4 = (const float4*)(x) + blockIdx.x * (BT * NQ / 4);
        float4* s4 = (float4*)sX;
        int total4 = (B * NQ) / 4 - blockIdx.x * (BT * NQ / 4);
#pragma unroll
        for (int i = 0; i < 3; ++i) {
            int e = i * BT + tid;
            s4[e] = (e < total4) ? x4[e] : make_float4(0.f, 0.f, 0.f, 0.f);
        }
    }

    // ---- fused gate U = RZ(c) RX(b) RY(a) per (layer, wire) ----------------
    for (int e = tid; e < 36; e += BT) {
        const float* p = params + e * 3;
        float sa, ca; sincosf(0.5f * p[0], &sa, &ca);
        float sb, cb; sincosf(0.5f * p[1], &sb, &cb);
        float sc, cc; sincosf(0.5f * p[2], &sc, &cc);
        float2 m00 = make_float2( cb * ca, -sb * sa);
        float2 m01 = make_float2(-cb * sa, -sb * ca);
        float2 m10 = make_float2( cb * sa, -sb * ca);
        float2 m11 = make_float2( cb * ca,  sb * sa);
        float2 e0 = make_float2(cc, -sc);
        float2 e1 = make_float2(cc,  sc);
        int layer = e / 12, wire = e % 12;
        sU[layer][wire][0] = cmulc(e0, m00);   // U[0][0]
        sU[layer][wire][1] = cmulc(e0, m01);   // U[0][1]
        sU[layer][wire][2] = cmulc(e1, m10);   // U[1][0]
        sU[layer][wire][3] = cmulc(e1, m11);   // U[1][1]
    }
    __syncthreads();

    // ---- K tensors: 352 bulk entries (p=1..11) + 16 boundary entries (p=0) -
    for (int e = tid; e < 368; e += BT) {
        if (e < 352) {
            int p   = e / 32 + 1;          // 1..11
            int w   = 11 - p;              // wire for bit p
            int rem = e % 32;
            int s   = rem >> 4;            // n-bit of this position
            int sg  = (rem >> 2) & 3;      // sigma  = a + 2b
            int sgp = rem & 3;             // sigma' = a' + 2b'
            int a = sg & 1,  bq = sg >> 1;
            int ap = sgp & 1, bp = sgp >> 1;
            sK[p - 1][s][sg][sgp] =
                cmulc(cmulc(sU[2][w][a],                      // U2[0][a]
                            sU[1][w][((a ^ ap) << 1) | bq]),  // U1[a^a'][b]
                      sU[0][w][((bq ^ bp) << 1) | s]);        // U0[b^b'][s]
        } else {
            int r   = e - 352;
            int j   = r >> 3;
            int s   = (r >> 2) & 1;
            int sgp = r & 3;
            int ap = sgp & 1, bp = sgp >> 1;
            float2 acc = make_float2(0.0f, 0.0f);
#pragma unroll
            for (int sg = 0; sg < 4; ++sg) {      // sum over sigma_0 (free)
                int a = sg & 1, bq = sg >> 1;
                acc = caddc(acc,
                    cmulc(cmulc(sU[2][11][(j << 1) | a],      // U2[j][a]
                                sU[1][11][((a ^ ap) << 1) | bq]),
                          sU[0][11][((bq ^ bp) << 1) | s]));
            }
            sKap[j][s][sgp] = acc;
        }
    }
    __syncthreads();

    // ---- per-batch transfer-matrix chain -----------------------------------
    const int b = blockIdx.x * BT + tid;

    float fc[NQ], fs[NQ];
#pragma unroll
    for (int w = 0; w < NQ; ++w) {
        float s, c; __sincosf(0.5f * sX[tid * NQ + w], &s, &c);
        fc[w] = c; fs[w] = s;
    }

    // p = 11 (wire 0): sigma_12 = 0 boundary -> column 0 of K_11
    float2 wv[4];
#pragma unroll
    for (int sg = 0; sg < 4; ++sg) {
        float2 k0 = sK[10][0][sg][0], k1 = sK[10][1][sg][0];
        wv[sg] = make_float2(fc[0] * k0.x + fs[0] * k1.x,
                             fc[0] * k0.y + fs[0] * k1.y);
    }

    // p = 10..1 (wire 11-p): w <- (c*K0 + s*K1) w
#pragma unroll
    for (int p = 10; p >= 1; --p) {
        float c = fc[11 - p], s = fs[11 - p];
        float2 nw[4];
#pragma unroll
        for (int sg = 0; sg < 4; ++sg) {
            float2 a0 = make_float2(0.0f, 0.0f);
            float2 a1 = make_float2(0.0f, 0.0f);
#pragma unroll
            for (int sp = 0; sp < 4; ++sp) {
                a0 = caddc(a0, cmulc(sK[p - 1][0][sg][sp], wv[sp]));
                a1 = caddc(a1, cmulc(sK[p - 1][1][sg][sp], wv[sp]));
            }
            nw[sg] = make_float2(c * a0.x + s * a1.x,
                                 c * a0.y + s * a1.y);
        }
#pragma unroll
        for (int sg = 0; sg < 4; ++sg) wv[sg] = nw[sg];
    }

    // p = 0 (wire 11): boundary row-sums, two j variants
    float pr[2];
#pragma unroll
    for (int j = 0; j < 2; ++j) {
        float2 a0 = make_float2(0.0f, 0.0f);
        float2 a1 = make_float2(0.0f, 0.0f);
#pragma unroll
        for (int sp = 0; sp < 4; ++sp) {
            a0 = caddc(a0, cmulc(sKap[j][0][sp], wv[sp]));
            a1 = caddc(a1, cmulc(sKap[j][1][sp], wv[sp]));
        }
        float re = fc[11] * a0.x + fs[11] * a1.x;
        float im = fc[11] * a0.y + fs[11] * a1.y;
        pr[j] = re * re + im * im;
    }

    if (b < B) {
        float inv = 1.0f / (pr[0] + pr[1]);
        ((float2*)out)[b] = make_float2(pr[0] * inv, pr[1] * inv);
    }
}

extern "C" void kernel_launch(void* const* d_in, const int* in_sizes, int n_in,
                              void* d_out, int out_size) {
    const float* x      = (const float*)d_in[0];  // (B, 12) float32
    const float* params = (const float*)d_in[1];  // (3, 12, 3) float32
    float* out = (float*)d_out;                   // (B, 2) float32
    int B = in_sizes[0] / NQ;

    qnn_mps_kernel<<<(B + BT - 1) / BT, BT>>>(x, params, out, B);
}